// round 3
// baseline (speedup 1.0000x reference)
#include <cuda_runtime.h>
#include <math.h>

#define HW 65536           // 256*256
#define IMG 256

// ---- scratch (device globals: allocation-free contract) ----
__device__ float g_h[134217728];   // [4][512][65536]  project_in output (512 MB)
__device__ float g_g[67108864];    // [4][256][65536]  glu output        (256 MB)
__device__ float g_y[16777216];    // [4][64][65536]   project_out output (64 MB)
__device__ float g_K[4096];        // [64][8][8]       spatial circular kernel

#define PROJ_SMEM 51200    // bytes of dynamic smem for both GEMM kernels

// ============================================================
// Kernel 1: project_in  h[b,o,p] = b_in[o] + sum_c w_in[o,c]*x[b,c,p]
// GEMM M=512 (o), K=64 (c), N=65536/batch.
// X tile (64c x 64px) loaded ONCE; loop 4 o-chunks of 128.
// Microtile 8o x 4px per thread. grid: (1024, 1, 4), block: 256
// Dynamic smem: Xs[64][68] then Wt[64][132]  (row strides 16B-aligned)
// ============================================================
__global__ __launch_bounds__(256) void k_proj_in(
    const float* __restrict__ x, const float* __restrict__ w,
    const float* __restrict__ bias)
{
    extern __shared__ float dyn[];
    float* Xs = dyn;               // [c][px] stride 68
    float* Wt = dyn + 64 * 68;     // [c][o]  stride 132 (%32=4 -> <=2-way transp. store)
    const int px0 = blockIdx.x * 64;
    const int b   = blockIdx.z;
    const int tid = threadIdx.x;
    const int tx  = tid & 15, ty = tid >> 4;

    // load X tile once (64 c x 64 px)
    const float* xb = x + (b * 64) * HW + px0;
    #pragma unroll
    for (int i = 0; i < 4; i++) {
        int idx = tid + i * 256;
        int c   = idx >> 4;
        int j4  = idx & 15;
        *(float4*)&Xs[c * 68 + j4 * 4] = *(const float4*)(xb + c * HW + j4 * 4);
    }

    for (int oc = 0; oc < 4; oc++) {
        const int o0 = oc * 128;
        // load W chunk (128 o x 64 c), transpose into Wt[c][o]
        #pragma unroll
        for (int i = 0; i < 8; i++) {
            int idx = tid + i * 256;       // 0..2047
            int o   = idx >> 4;            // 0..127
            int c4  = idx & 15;
            float4 v = *(const float4*)(w + (o0 + o) * 64 + c4 * 4);
            Wt[(c4*4+0) * 132 + o] = v.x; Wt[(c4*4+1) * 132 + o] = v.y;
            Wt[(c4*4+2) * 132 + o] = v.z; Wt[(c4*4+3) * 132 + o] = v.w;
        }
        __syncthreads();

        float acc[8][4] = {};
        #pragma unroll 8
        for (int k = 0; k < 64; k++) {
            float a[8];
            *(float4*)&a[0] = *(float4*)&Wt[k * 132 + ty*8];
            *(float4*)&a[4] = *(float4*)&Wt[k * 132 + ty*8 + 4];
            float4 bv = *(float4*)&Xs[k * 68 + tx*4];
            float bb[4] = {bv.x, bv.y, bv.z, bv.w};
            #pragma unroll
            for (int i = 0; i < 8; i++)
                #pragma unroll
                for (int j = 0; j < 4; j++)
                    acc[i][j] += a[i] * bb[j];
        }
        __syncthreads();   // done reading Wt before next chunk overwrites it

        #pragma unroll
        for (int i = 0; i < 8; i++) {
            int o = o0 + ty*8 + i;
            float bz = bias[o];
            float4 r;
            r.x = acc[i][0] + bz; r.y = acc[i][1] + bz;
            r.z = acc[i][2] + bz; r.w = acc[i][3] + bz;
            *(float4*)&g_h[(b * 512 + o) * HW + px0 + tx*4] = r;
        }
    }
}

// ============================================================
// Kernel 2: depthwise 3x3 (SAME, zero pad) + bias + exact-GELU gate
// out g[b,g,p] = gelu(conv(h[b,g]) + bdw[g]) * (conv(h[b,g+256]) + bdw[g+256])
// tile 16 rows x 64 cols, halo 1. grid: (4, 16, 1024=B*256), block: 256
// ============================================================
__global__ __launch_bounds__(256) void k_dw_glu(
    const float* __restrict__ wdw, const float* __restrict__ bdw)
{
    __shared__ float s1[18][66];
    __shared__ float s2[18][66];
    const int w0 = blockIdx.x * 64;
    const int h0 = blockIdx.y * 16;
    const int b  = blockIdx.z >> 8;
    const int g  = blockIdx.z & 255;
    const int tid = threadIdx.x;

    const float* h1 = g_h + (b * 512 + g) * HW;
    const float* h2 = g_h + (b * 512 + g + 256) * HW;
    for (int idx = tid; idx < 18 * 66; idx += 256) {
        int r  = idx / 66, cc = idx % 66;
        int gy = h0 + r - 1, gx = w0 + cc - 1;
        float v1 = 0.f, v2 = 0.f;
        if (gy >= 0 && gy < IMG && gx >= 0 && gx < IMG) {
            int off = gy * IMG + gx;
            v1 = h1[off];
            v2 = h2[off];
        }
        s1[r][cc] = v1;
        s2[r][cc] = v2;
    }
    __syncthreads();

    float wa[9], wb[9];
    #pragma unroll
    for (int i = 0; i < 9; i++) { wa[i] = wdw[g*9 + i]; wb[i] = wdw[(g+256)*9 + i]; }
    const float ba = bdw[g], bb2 = bdw[g + 256];

    const int r  = tid >> 4;          // 0..15
    const int c0 = (tid & 15) * 4;    // 0..60
    float o1[4] = {ba, ba, ba, ba};
    float o2[4] = {bb2, bb2, bb2, bb2};
    #pragma unroll
    for (int ky = 0; ky < 3; ky++) {
        float v1[6], v2[6];
        #pragma unroll
        for (int j = 0; j < 6; j++) { v1[j] = s1[r+ky][c0+j]; v2[j] = s2[r+ky][c0+j]; }
        #pragma unroll
        for (int q = 0; q < 4; q++)
            #pragma unroll
            for (int kx = 0; kx < 3; kx++) {
                o1[q] += v1[q+kx] * wa[ky*3 + kx];
                o2[q] += v2[q+kx] * wb[ky*3 + kx];
            }
    }
    float4 res;
    float* rp = &res.x;
    #pragma unroll
    for (int q = 0; q < 4; q++) {
        float a  = o1[q];
        float ge = 0.5f * a * (1.0f + erff(a * 0.70710678118654752f));
        rp[q] = ge * o2[q];
    }
    *(float4*)&g_g[(b * 256 + g) * HW + (h0 + r) * IMG + w0 + c0] = res;
}

// ============================================================
// Kernel 3: project_out  y[b,o,p] = b_out[o] + sum_g w_out[o,g]*g[b,g,p]
// GEMM M=64, K=256 (4 chunks of 64), N=65536/batch.
// px tile 128, microtile 4o x 8px. grid: (512, 1, 4), block: 256
// Dynamic smem: Wt[64][68] then Xs[64][132]
// ============================================================
__global__ __launch_bounds__(256) void k_proj_out(
    const float* __restrict__ w, const float* __restrict__ bias)
{
    extern __shared__ float dyn[];
    float* Wt = dyn;               // [k][o]  stride 68
    float* Xs = dyn + 64 * 68;     // [k][px] stride 132
    const int px0 = blockIdx.x * 128;
    const int b   = blockIdx.z;
    const int tid = threadIdx.x;
    const int tx  = tid & 15, ty = tid >> 4;

    float acc[4][8] = {};
    for (int kc = 0; kc < 4; kc++) {
        const int k0 = kc * 64;
        // W chunk (64 o x 64 k), transposed
        #pragma unroll
        for (int i = 0; i < 4; i++) {
            int idx = tid + i * 256;
            int o   = idx >> 4;
            int c4  = idx & 15;
            float4 v = *(const float4*)(w + o * 256 + k0 + c4 * 4);
            Wt[(c4*4+0) * 68 + o] = v.x; Wt[(c4*4+1) * 68 + o] = v.y;
            Wt[(c4*4+2) * 68 + o] = v.z; Wt[(c4*4+3) * 68 + o] = v.w;
        }
        // X chunk (64 k x 128 px)
        const float* gb = g_g + (b * 256 + k0) * HW + px0;
        #pragma unroll
        for (int i = 0; i < 8; i++) {
            int idx = tid + i * 256;
            int c   = idx >> 5;
            int j4  = idx & 31;
            *(float4*)&Xs[c * 132 + j4 * 4] = *(const float4*)(gb + c * HW + j4 * 4);
        }
        __syncthreads();

        #pragma unroll 8
        for (int k = 0; k < 64; k++) {
            float a[4];
            *(float4*)&a[0] = *(float4*)&Wt[k * 68 + ty*4];
            float4 b0 = *(float4*)&Xs[k * 132 + tx*4];
            float4 b1 = *(float4*)&Xs[k * 132 + 64 + tx*4];
            float bb[8] = {b0.x, b0.y, b0.z, b0.w, b1.x, b1.y, b1.z, b1.w};
            #pragma unroll
            for (int i = 0; i < 4; i++)
                #pragma unroll
                for (int j = 0; j < 8; j++)
                    acc[i][j] += a[i] * bb[j];
        }
        __syncthreads();
    }
    #pragma unroll
    for (int i = 0; i < 4; i++) {
        int o = ty*4 + i;
        float bz = bias[o];
        float4 r0, r1;
        r0.x = acc[i][0] + bz; r0.y = acc[i][1] + bz;
        r0.z = acc[i][2] + bz; r0.w = acc[i][3] + bz;
        r1.x = acc[i][4] + bz; r1.y = acc[i][5] + bz;
        r1.z = acc[i][6] + bz; r1.w = acc[i][7] + bz;
        float* op = &g_y[(b * 64 + o) * HW + px0];
        *(float4*)(op + tx*4)      = r0;
        *(float4*)(op + 64 + tx*4) = r1;
    }
}

// ============================================================
// Kernel 4: build spatial circular kernel K[ch] = IDFT2(hermitian-ext(filter))
// filter [64,1,1,8,5] real, applied to rfft2 coefficients.
// Full-spectrum: G[k1][k2] = F[k1][k2] (k2<=4) else F[(8-k1)%8][8-k2]
// K[n1][n2] = (1/64) sum G[k1][k2] * cos(2*pi*(k1*n1 + k2*n2)/8)
// grid: (16), block: 256
// ============================================================
__global__ void k_build_filter(const float* __restrict__ f)
{
    int t = blockIdx.x * 256 + threadIdx.x;
    if (t >= 4096) return;
    int ch = t >> 6;
    int a  = (t >> 3) & 7;
    int bb = t & 7;
    const float R = 0.70710678118654752f;
    const float ctab[8] = {1.f, R, 0.f, -R, -1.f, -R, 0.f, R};
    float s = 0.f;
    #pragma unroll
    for (int k1 = 0; k1 < 8; k1++)
        #pragma unroll
        for (int k2 = 0; k2 < 8; k2++) {
            float G = (k2 <= 4) ? f[ch*40 + k1*5 + k2]
                                : f[ch*40 + ((8-k1) & 7)*5 + (8 - k2)];
            s += G * ctab[(k1*a + k2*bb) & 7];
        }
    g_K[t] = s * (1.f / 64.f);
}

// ============================================================
// Kernel 5: per-8x8-patch circular convolution with K[ch], write final output.
// Block covers an 8-row x 256-col strip (32 patches). Thread owns one patch
// row (8 outputs) so all register indices are compile-time.
// grid: (1, 32, 256=B*64), block: 256
// ============================================================
__global__ __launch_bounds__(256) void k_patch(float* __restrict__ out)
{
    __shared__ float s[8][257];   // pad -> conflict-free strided reads
    __shared__ float Ks[64];
    const int h0 = blockIdx.y * 8;
    const int b  = blockIdx.z >> 6;
    const int ch = blockIdx.z & 63;
    const int tid = threadIdx.x;

    const float* yc = g_y + (b * 64 + ch) * HW;
    if (tid < 64) Ks[tid] = g_K[ch * 64 + tid];
    #pragma unroll
    for (int i = 0; i < 8; i++) {
        int idx = tid + i * 256;
        int r = idx >> 8, c = idx & 255;
        s[r][c] = yc[(h0 + r) * IMG + c];
    }
    __syncthreads();

    const int n1 = tid & 7;       // output row within patch
    const int pw = tid >> 3;      // patch index along W (0..31)
    const int pb = pw * 8;
    float acc[8] = {};
    #pragma unroll
    for (int d1 = 0; d1 < 8; d1++) {
        int r = (n1 - d1) & 7;
        float riv[8];
        #pragma unroll
        for (int j = 0; j < 8; j++) riv[j] = s[r][pb + j];
        #pragma unroll
        for (int d2 = 0; d2 < 8; d2++) {
            float kv = Ks[d1*8 + d2];
            #pragma unroll
            for (int c2 = 0; c2 < 8; c2++)
                acc[c2] += kv * riv[(c2 - d2) & 7];
        }
    }
    float* op = out + (b * 64 + ch) * HW + (h0 + n1) * IMG + pb;
    float4 r0 = make_float4(acc[0], acc[1], acc[2], acc[3]);
    float4 r1 = make_float4(acc[4], acc[5], acc[6], acc[7]);
    *(float4*)op       = r0;
    *(float4*)(op + 4) = r1;
}

// ============================================================
extern "C" void kernel_launch(void* const* d_in, const int* in_sizes, int n_in,
                              void* d_out, int out_size)
{
    const float* x     = (const float*)d_in[0];
    const float* w_in  = (const float*)d_in[1];
    const float* b_in  = (const float*)d_in[2];
    const float* w_dw  = (const float*)d_in[3];
    const float* b_dw  = (const float*)d_in[4];
    const float* w_out = (const float*)d_in[5];
    const float* b_out = (const float*)d_in[6];
    const float* fftf  = (const float*)d_in[7];
    float* out = (float*)d_out;

    // opt in to >48KB dynamic smem (host-side, not stream-ordered: capture-safe)
    cudaFuncSetAttribute(k_proj_in,  cudaFuncAttributeMaxDynamicSharedMemorySize, PROJ_SMEM);
    cudaFuncSetAttribute(k_proj_out, cudaFuncAttributeMaxDynamicSharedMemorySize, PROJ_SMEM);

    k_build_filter<<<16, 256>>>(fftf);
    k_proj_in<<<dim3(1024, 1, 4), 256, PROJ_SMEM>>>(x, w_in, b_in);
    k_dw_glu<<<dim3(4, 16, 1024), 256>>>(w_dw, b_dw);
    k_proj_out<<<dim3(512, 1, 4), 256, PROJ_SMEM>>>(w_out, b_out);
    k_patch<<<dim3(1, 32, 256), 256>>>(out);
}

// round 4
// speedup vs baseline: 1.1210x; 1.1210x over previous
#include <cuda_runtime.h>
#include <math.h>

#define HW 65536           // 256*256
#define IMG 256

// ---- scratch (device globals: allocation-free contract) ----
__device__ float g_h[134217728];   // [4][512][65536]  project_in output (512 MB)
__device__ float g_g[67108864];    // [4][256][65536]  glu output        (256 MB)
__device__ float g_y[16777216];    // [4][64][65536]   project_out output (64 MB)
__device__ float g_K[4096];        // [64][8][8]       spatial circular kernel
__device__ float g_wt[32768];      // w_in^T  [c=64][o=512]
__device__ float g_w2t[16384];     // w_out^T [k=256][o=64]

// packed fp32x2 FMA (Blackwell FFMA2; 2x fp32 rate vs scalar FFMA)
#define FFMA2(d, a, b) asm("fma.rn.f32x2 %0, %1, %2, %0;" : "+l"(d) : "l"(a), "l"(b))
#define DUP2(d, f)     asm("mov.b64 %0, {%1, %1};" : "=l"(d) : "r"(__float_as_uint(f)))
#define UNPK2(lo, hi, d) asm("mov.b64 {%0, %1}, %2;" : "=r"(lo), "=r"(hi) : "l"(d))

#define PI_SMEM  (2 * 64 * 132 * 4)          // proj_in: Xs[64][132] + Wt[64][132] = 67.6KB
#define PO_SMEM  ((64 * 264 + 64 * 68) * 4)  // proj_out: Xs[64][264] + Wt[64][68] = 85KB

// ============================================================
// Kernel 0: one-time weight transposes (tiny)
// ============================================================
__global__ void k_transpose(const float* __restrict__ w_in,
                            const float* __restrict__ w_out)
{
    int t = blockIdx.x * 256 + threadIdx.x;
    if (t < 32768) { int o = t >> 6, c = t & 63;  g_wt[c * 512 + o] = w_in[t]; }
    if (t < 16384) { int o = t >> 8, k = t & 255; g_w2t[k * 64 + o] = w_out[t]; }
}

// ============================================================
// Kernel 1: project_in  h[b,o,p] = b_in[o] + sum_c w_in[o,c]*x[b,c,p]
// M=512, K=64, N=65536/batch. px tile 128 (X loaded once), 4 o-chunks of 128.
// Thread tile 8o x 8px, FFMA2 packed px-pairs. grid (512,1,4), block 256.
// ============================================================
__global__ __launch_bounds__(256) void k_proj_in(
    const float* __restrict__ x, const float* __restrict__ bias)
{
    extern __shared__ float dyn[];
    float* Xs = dyn;               // [c][px] stride 132
    float* Wt = dyn + 64 * 132;    // [c][o]  stride 132
    const int px0 = blockIdx.x * 128;
    const int b   = blockIdx.z;
    const int tid = threadIdx.x;
    const int tx  = tid & 15, ty = tid >> 4;

    // load X tile once (64 c x 128 px), coalesced
    const float* xb = x + (b * 64) * HW + px0;
    #pragma unroll
    for (int i = 0; i < 8; i++) {
        int idx = tid + i * 256;       // 0..2047
        int c   = idx >> 5;            // 0..63
        int j4  = idx & 31;            // 0..31
        *(float4*)&Xs[c * 132 + j4 * 4] = *(const float4*)(xb + c * HW + j4 * 4);
    }

    for (int oc = 0; oc < 4; oc++) {
        const int o0 = oc * 128;
        // load W^T chunk (64 c x 128 o), coalesced, conflict-free stores
        #pragma unroll
        for (int i = 0; i < 8; i++) {
            int idx = tid + i * 256;
            int c   = idx >> 5;
            int j4  = idx & 31;
            *(float4*)&Wt[c * 132 + j4 * 4] =
                *(const float4*)(g_wt + c * 512 + o0 + j4 * 4);
        }
        __syncthreads();

        unsigned long long acc[8][4];
        #pragma unroll
        for (int i = 0; i < 8; i++)
            #pragma unroll
            for (int j = 0; j < 4; j++) acc[i][j] = 0ull;

        #pragma unroll 8
        for (int k = 0; k < 64; k++) {
            float4 a0 = *(float4*)&Wt[k * 132 + ty * 8];
            float4 a1 = *(float4*)&Wt[k * 132 + ty * 8 + 4];
            longlong2 b0 = *(longlong2*)&Xs[k * 132 + tx * 4];
            longlong2 b1 = *(longlong2*)&Xs[k * 132 + 64 + tx * 4];
            unsigned long long p0 = (unsigned long long)b0.x;
            unsigned long long p1 = (unsigned long long)b0.y;
            unsigned long long p2 = (unsigned long long)b1.x;
            unsigned long long p3 = (unsigned long long)b1.y;
            unsigned long long a2[8];
            DUP2(a2[0], a0.x); DUP2(a2[1], a0.y); DUP2(a2[2], a0.z); DUP2(a2[3], a0.w);
            DUP2(a2[4], a1.x); DUP2(a2[5], a1.y); DUP2(a2[6], a1.z); DUP2(a2[7], a1.w);
            #pragma unroll
            for (int i = 0; i < 8; i++) {
                FFMA2(acc[i][0], a2[i], p0);
                FFMA2(acc[i][1], a2[i], p1);
                FFMA2(acc[i][2], a2[i], p2);
                FFMA2(acc[i][3], a2[i], p3);
            }
        }
        __syncthreads();   // done reading Wt before next chunk overwrites it

        #pragma unroll
        for (int i = 0; i < 8; i++) {
            int o = o0 + ty * 8 + i;
            float bz = bias[o];
            unsigned r0, r1, r2, r3, r4, r5, r6, r7;
            UNPK2(r0, r1, acc[i][0]); UNPK2(r2, r3, acc[i][1]);
            UNPK2(r4, r5, acc[i][2]); UNPK2(r6, r7, acc[i][3]);
            float4 v0 = make_float4(__uint_as_float(r0) + bz, __uint_as_float(r1) + bz,
                                    __uint_as_float(r2) + bz, __uint_as_float(r3) + bz);
            float4 v1 = make_float4(__uint_as_float(r4) + bz, __uint_as_float(r5) + bz,
                                    __uint_as_float(r6) + bz, __uint_as_float(r7) + bz);
            float* op = &g_h[(b * 512 + o) * HW + px0];
            *(float4*)(op + tx * 4)      = v0;
            *(float4*)(op + 64 + tx * 4) = v1;
        }
    }
}

// ============================================================
// Kernel 2: depthwise 3x3 (SAME) + bias + exact-GELU gate  (unchanged)
// grid (4, 16, 1024=B*256), block 256
// ============================================================
__global__ __launch_bounds__(256) void k_dw_glu(
    const float* __restrict__ wdw, const float* __restrict__ bdw)
{
    __shared__ float s1[18][66];
    __shared__ float s2[18][66];
    const int w0 = blockIdx.x * 64;
    const int h0 = blockIdx.y * 16;
    const int b  = blockIdx.z >> 8;
    const int g  = blockIdx.z & 255;
    const int tid = threadIdx.x;

    const float* h1 = g_h + (b * 512 + g) * HW;
    const float* h2 = g_h + (b * 512 + g + 256) * HW;
    for (int idx = tid; idx < 18 * 66; idx += 256) {
        int r  = idx / 66, cc = idx % 66;
        int gy = h0 + r - 1, gx = w0 + cc - 1;
        float v1 = 0.f, v2 = 0.f;
        if (gy >= 0 && gy < IMG && gx >= 0 && gx < IMG) {
            int off = gy * IMG + gx;
            v1 = h1[off];
            v2 = h2[off];
        }
        s1[r][cc] = v1;
        s2[r][cc] = v2;
    }
    __syncthreads();

    float wa[9], wb[9];
    #pragma unroll
    for (int i = 0; i < 9; i++) { wa[i] = wdw[g*9 + i]; wb[i] = wdw[(g+256)*9 + i]; }
    const float ba = bdw[g], bb2 = bdw[g + 256];

    const int r  = tid >> 4;
    const int c0 = (tid & 15) * 4;
    float o1[4] = {ba, ba, ba, ba};
    float o2[4] = {bb2, bb2, bb2, bb2};
    #pragma unroll
    for (int ky = 0; ky < 3; ky++) {
        float v1[6], v2[6];
        #pragma unroll
        for (int j = 0; j < 6; j++) { v1[j] = s1[r+ky][c0+j]; v2[j] = s2[r+ky][c0+j]; }
        #pragma unroll
        for (int q = 0; q < 4; q++)
            #pragma unroll
            for (int kx = 0; kx < 3; kx++) {
                o1[q] += v1[q+kx] * wa[ky*3 + kx];
                o2[q] += v2[q+kx] * wb[ky*3 + kx];
            }
    }
    float4 res;
    float* rp = &res.x;
    #pragma unroll
    for (int q = 0; q < 4; q++) {
        float a  = o1[q];
        float ge = 0.5f * a * (1.0f + erff(a * 0.70710678118654752f));
        rp[q] = ge * o2[q];
    }
    *(float4*)&g_g[(b * 256 + g) * HW + (h0 + r) * IMG + w0 + c0] = res;
}

// ============================================================
// Kernel 3: project_out  y[b,o,p] = b_out[o] + sum_g w_out[o,g]*g[b,g,p]
// M=64, K=256 (4 chunks), N=65536/batch. px tile 256, thread tile 8o x 8px,
// FFMA2 packed. grid (256,1,4), block 256.
// ============================================================
__global__ __launch_bounds__(256) void k_proj_out(
    const float* __restrict__ bias)
{
    extern __shared__ float dyn[];
    float* Xs = dyn;               // [k][px] stride 264
    float* Wt = dyn + 64 * 264;    // [k][o]  stride 68
    const int px0 = blockIdx.x * 256;
    const int b   = blockIdx.z;
    const int tid = threadIdx.x;
    const int tx  = tid & 31, ty = tid >> 5;

    unsigned long long acc[8][4];
    #pragma unroll
    for (int i = 0; i < 8; i++)
        #pragma unroll
        for (int j = 0; j < 4; j++) acc[i][j] = 0ull;

    for (int kc = 0; kc < 4; kc++) {
        const int k0 = kc * 64;
        // W^T chunk (64 k x 64 o), coalesced
        {
            int c  = tid >> 2;          // wait: 64 rows x 16 float4 = 1024 loads
            int j4 = tid & 3;
            #pragma unroll
            for (int i = 0; i < 4; i++) {
                int cc = c + i * 64;    // c 0..63 over 4 iters? no: c in 0..63 already
                // use flat mapping instead
            }
        }
        // flat: 64k x 64o = 4096 floats = 1024 float4
        #pragma unroll
        for (int i = 0; i < 4; i++) {
            int idx = tid + i * 256;    // 0..1023
            int kk  = idx >> 4;
            int j4  = idx & 15;
            *(float4*)&Wt[kk * 68 + j4 * 4] =
                *(const float4*)(g_w2t + (k0 + kk) * 64 + j4 * 4);
        }
        // X chunk (64 k x 256 px)
        const float* gb = g_g + (b * 256 + k0) * HW + px0;
        #pragma unroll
        for (int i = 0; i < 16; i++) {
            int idx = tid + i * 256;    // 0..4095
            int kk  = idx >> 6;
            int j4  = idx & 63;
            *(float4*)&Xs[kk * 264 + j4 * 4] = *(const float4*)(gb + kk * HW + j4 * 4);
        }
        __syncthreads();

        #pragma unroll 8
        for (int k = 0; k < 64; k++) {
            float4 a0 = *(float4*)&Wt[k * 68 + ty * 8];
            float4 a1 = *(float4*)&Wt[k * 68 + ty * 8 + 4];
            longlong2 b0 = *(longlong2*)&Xs[k * 264 + tx * 4];
            longlong2 b1 = *(longlong2*)&Xs[k * 264 + 128 + tx * 4];
            unsigned long long p0 = (unsigned long long)b0.x;
            unsigned long long p1 = (unsigned long long)b0.y;
            unsigned long long p2 = (unsigned long long)b1.x;
            unsigned long long p3 = (unsigned long long)b1.y;
            unsigned long long a2[8];
            DUP2(a2[0], a0.x); DUP2(a2[1], a0.y); DUP2(a2[2], a0.z); DUP2(a2[3], a0.w);
            DUP2(a2[4], a1.x); DUP2(a2[5], a1.y); DUP2(a2[6], a1.z); DUP2(a2[7], a1.w);
            #pragma unroll
            for (int i = 0; i < 8; i++) {
                FFMA2(acc[i][0], a2[i], p0);
                FFMA2(acc[i][1], a2[i], p1);
                FFMA2(acc[i][2], a2[i], p2);
                FFMA2(acc[i][3], a2[i], p3);
            }
        }
        __syncthreads();
    }
    #pragma unroll
    for (int i = 0; i < 8; i++) {
        int o = ty * 8 + i;
        float bz = bias[o];
        unsigned r0, r1, r2, r3, r4, r5, r6, r7;
        UNPK2(r0, r1, acc[i][0]); UNPK2(r2, r3, acc[i][1]);
        UNPK2(r4, r5, acc[i][2]); UNPK2(r6, r7, acc[i][3]);
        float4 v0 = make_float4(__uint_as_float(r0) + bz, __uint_as_float(r1) + bz,
                                __uint_as_float(r2) + bz, __uint_as_float(r3) + bz);
        float4 v1 = make_float4(__uint_as_float(r4) + bz, __uint_as_float(r5) + bz,
                                __uint_as_float(r6) + bz, __uint_as_float(r7) + bz);
        float* op = &g_y[(b * 64 + o) * HW + px0];
        *(float4*)(op + tx * 4)       = v0;
        *(float4*)(op + 128 + tx * 4) = v1;
    }
}

// ============================================================
// Kernel 4: build spatial circular kernel (unchanged)
// ============================================================
__global__ void k_build_filter(const float* __restrict__ f)
{
    int t = blockIdx.x * 256 + threadIdx.x;
    if (t >= 4096) return;
    int ch = t >> 6;
    int a  = (t >> 3) & 7;
    int bb = t & 7;
    const float R = 0.70710678118654752f;
    const float ctab[8] = {1.f, R, 0.f, -R, -1.f, -R, 0.f, R};
    float s = 0.f;
    #pragma unroll
    for (int k1 = 0; k1 < 8; k1++)
        #pragma unroll
        for (int k2 = 0; k2 < 8; k2++) {
            float G = (k2 <= 4) ? f[ch*40 + k1*5 + k2]
                                : f[ch*40 + ((8-k1) & 7)*5 + (8 - k2)];
            s += G * ctab[(k1*a + k2*bb) & 7];
        }
    g_K[t] = s * (1.f / 64.f);
}

// ============================================================
// Kernel 5: per-8x8-patch circular convolution (unchanged)
// ============================================================
__global__ __launch_bounds__(256) void k_patch(float* __restrict__ out)
{
    __shared__ float s[8][257];
    __shared__ float Ks[64];
    const int h0 = blockIdx.y * 8;
    const int b  = blockIdx.z >> 6;
    const int ch = blockIdx.z & 63;
    const int tid = threadIdx.x;

    const float* yc = g_y + (b * 64 + ch) * HW;
    if (tid < 64) Ks[tid] = g_K[ch * 64 + tid];
    #pragma unroll
    for (int i = 0; i < 8; i++) {
        int idx = tid + i * 256;
        int r = idx >> 8, c = idx & 255;
        s[r][c] = yc[(h0 + r) * IMG + c];
    }
    __syncthreads();

    const int n1 = tid & 7;
    const int pw = tid >> 3;
    const int pb = pw * 8;
    float acc[8] = {};
    #pragma unroll
    for (int d1 = 0; d1 < 8; d1++) {
        int r = (n1 - d1) & 7;
        float riv[8];
        #pragma unroll
        for (int j = 0; j < 8; j++) riv[j] = s[r][pb + j];
        #pragma unroll
        for (int d2 = 0; d2 < 8; d2++) {
            float kv = Ks[d1*8 + d2];
            #pragma unroll
            for (int c2 = 0; c2 < 8; c2++)
                acc[c2] += kv * riv[(c2 - d2) & 7];
        }
    }
    float* op = out + (b * 64 + ch) * HW + (h0 + n1) * IMG + pb;
    *(float4*)op       = make_float4(acc[0], acc[1], acc[2], acc[3]);
    *(float4*)(op + 4) = make_float4(acc[4], acc[5], acc[6], acc[7]);
}

// ============================================================
extern "C" void kernel_launch(void* const* d_in, const int* in_sizes, int n_in,
                              void* d_out, int out_size)
{
    const float* x     = (const float*)d_in[0];
    const float* w_in  = (const float*)d_in[1];
    const float* b_in  = (const float*)d_in[2];
    const float* w_dw  = (const float*)d_in[3];
    const float* b_dw  = (const float*)d_in[4];
    const float* w_out = (const float*)d_in[5];
    const float* b_out = (const float*)d_in[6];
    const float* fftf  = (const float*)d_in[7];
    float* out = (float*)d_out;

    cudaFuncSetAttribute(k_proj_in,  cudaFuncAttributeMaxDynamicSharedMemorySize, PI_SMEM);
    cudaFuncSetAttribute(k_proj_out, cudaFuncAttributeMaxDynamicSharedMemorySize, PO_SMEM);

    k_build_filter<<<16, 256>>>(fftf);
    k_transpose<<<128, 256>>>(w_in, w_out);
    k_proj_in<<<dim3(512, 1, 4), 256, PI_SMEM>>>(x, b_in);
    k_dw_glu<<<dim3(4, 16, 1024), 256>>>(w_dw, b_dw);
    k_proj_out<<<dim3(256, 1, 4), 256, PO_SMEM>>>(b_out);
    k_patch<<<dim3(1, 32, 256), 256>>>(out);
}

// round 5
// speedup vs baseline: 1.2692x; 1.1322x over previous
#include <cuda_runtime.h>
#include <math.h>

#define HW 65536           // 256*256
#define IMG 256

// ---- scratch (device globals: allocation-free contract) ----
__device__ float g_h[134217728];   // [4][512][65536]  project_in output (512 MB)
__device__ float g_g[67108864];    // [4][256][65536]  glu output        (256 MB)
__device__ float g_y[16777216];    // [4][64][65536]   project_out output (64 MB)
__device__ float g_K[4096];        // [64][8][8]       spatial circular kernel
__device__ float g_wt[32768];      // w_in^T  [c=64][o=512]
__device__ float g_w2t[16384];     // w_out^T [k=256][o=64]

// packed fp32x2 FMA (Blackwell FFMA2; 2x fp32 rate vs scalar FFMA)
#define FFMA2(d, a, b) asm("fma.rn.f32x2 %0, %1, %2, %0;" : "+l"(d) : "l"(a), "l"(b))
#define DUP2(d, f)     asm("mov.b64 %0, {%1, %1};" : "=l"(d) : "r"(__float_as_uint(f)))
#define UNPK2(lo, hi, d) asm("mov.b64 {%0, %1}, %2;" : "=r"(lo), "=r"(hi) : "l"(d))

#define PI_SMEM  (2 * 64 * 132 * 4)          // proj_in: Xs[64][132] + Wt[64][132]
#define PO_SMEM  ((64 * 264 + 64 * 68) * 4)  // proj_out: Xs[64][264] + Wt[64][68]

// ============================================================
// Kernel 0: one-time weight transposes (tiny)
// ============================================================
__global__ void k_transpose(const float* __restrict__ w_in,
                            const float* __restrict__ w_out)
{
    int t = blockIdx.x * 256 + threadIdx.x;
    if (t < 32768) { int o = t >> 6, c = t & 63;  g_wt[c * 512 + o] = w_in[t]; }
    if (t < 16384) { int o = t >> 8, k = t & 255; g_w2t[k * 64 + o] = w_out[t]; }
}

// ============================================================
// Kernel 1: project_in  h[b,o,p] = b_in[o] + sum_c w_in[o,c]*x[b,c,p]
// M=512, K=64, N=65536/batch. px tile 128 (X loaded once), 4 o-chunks of 128.
// Thread tile 8o x 8px, FFMA2. grid (512,1,4), block 256.
// ============================================================
__global__ __launch_bounds__(256) void k_proj_in(
    const float* __restrict__ x, const float* __restrict__ bias)
{
    extern __shared__ float dyn[];
    float* Xs = dyn;               // [c][px] stride 132
    float* Wt = dyn + 64 * 132;    // [c][o]  stride 132
    const int px0 = blockIdx.x * 128;
    const int b   = blockIdx.z;
    const int tid = threadIdx.x;
    const int tx  = tid & 15, ty = tid >> 4;

    const float* xb = x + (b * 64) * HW + px0;
    #pragma unroll
    for (int i = 0; i < 8; i++) {
        int idx = tid + i * 256;
        int c   = idx >> 5;
        int j4  = idx & 31;
        *(float4*)&Xs[c * 132 + j4 * 4] = *(const float4*)(xb + c * HW + j4 * 4);
    }

    for (int oc = 0; oc < 4; oc++) {
        const int o0 = oc * 128;
        #pragma unroll
        for (int i = 0; i < 8; i++) {
            int idx = tid + i * 256;
            int c   = idx >> 5;
            int j4  = idx & 31;
            *(float4*)&Wt[c * 132 + j4 * 4] =
                *(const float4*)(g_wt + c * 512 + o0 + j4 * 4);
        }
        __syncthreads();

        unsigned long long acc[8][4];
        #pragma unroll
        for (int i = 0; i < 8; i++)
            #pragma unroll
            for (int j = 0; j < 4; j++) acc[i][j] = 0ull;

        #pragma unroll 8
        for (int k = 0; k < 64; k++) {
            float4 a0 = *(float4*)&Wt[k * 132 + ty * 8];
            float4 a1 = *(float4*)&Wt[k * 132 + ty * 8 + 4];
            longlong2 b0 = *(longlong2*)&Xs[k * 132 + tx * 4];
            longlong2 b1 = *(longlong2*)&Xs[k * 132 + 64 + tx * 4];
            unsigned long long p0 = (unsigned long long)b0.x;
            unsigned long long p1 = (unsigned long long)b0.y;
            unsigned long long p2 = (unsigned long long)b1.x;
            unsigned long long p3 = (unsigned long long)b1.y;
            unsigned long long a2[8];
            DUP2(a2[0], a0.x); DUP2(a2[1], a0.y); DUP2(a2[2], a0.z); DUP2(a2[3], a0.w);
            DUP2(a2[4], a1.x); DUP2(a2[5], a1.y); DUP2(a2[6], a1.z); DUP2(a2[7], a1.w);
            #pragma unroll
            for (int i = 0; i < 8; i++) {
                FFMA2(acc[i][0], a2[i], p0);
                FFMA2(acc[i][1], a2[i], p1);
                FFMA2(acc[i][2], a2[i], p2);
                FFMA2(acc[i][3], a2[i], p3);
            }
        }
        __syncthreads();

        #pragma unroll
        for (int i = 0; i < 8; i++) {
            int o = o0 + ty * 8 + i;
            float bz = bias[o];
            unsigned r0, r1, r2, r3, r4, r5, r6, r7;
            UNPK2(r0, r1, acc[i][0]); UNPK2(r2, r3, acc[i][1]);
            UNPK2(r4, r5, acc[i][2]); UNPK2(r6, r7, acc[i][3]);
            float4 v0 = make_float4(__uint_as_float(r0) + bz, __uint_as_float(r1) + bz,
                                    __uint_as_float(r2) + bz, __uint_as_float(r3) + bz);
            float4 v1 = make_float4(__uint_as_float(r4) + bz, __uint_as_float(r5) + bz,
                                    __uint_as_float(r6) + bz, __uint_as_float(r7) + bz);
            float* op = &g_h[(b * 512 + o) * HW + px0];
            *(float4*)(op + tx * 4)      = v0;
            *(float4*)(op + 64 + tx * 4) = v1;
        }
    }
}

// ============================================================
// Kernel 2: depthwise 3x3 (SAME) + bias + exact-GELU gate — full-row tiles.
// Tile = 256 cols (whole row) x 8 output rows; halo = 2 zero columns + row
// predicate. Thread tid owns column tid, slides 3x3 down 10 smem rows.
// grid (32, 1024=B*256), block 256.
// ============================================================
__global__ __launch_bounds__(256) void k_dw_glu(
    const float* __restrict__ wdw, const float* __restrict__ bdw)
{
    __shared__ float s1[10][264];
    __shared__ float s2[10][264];
    const int h0 = blockIdx.x * 8;
    const int b  = blockIdx.y >> 8;
    const int g  = blockIdx.y & 255;
    const int tid = threadIdx.x;

    const float* h1 = g_h + (b * 512 + g) * HW;
    const float* h2 = g_h + (b * 512 + g + 256) * HW;

    #pragma unroll
    for (int r = 0; r < 10; r++) {
        int gy = h0 + r - 1;
        bool v = (gy >= 0) & (gy < IMG);
        int off = gy * IMG + tid;
        s1[r][tid + 1] = v ? h1[off] : 0.f;
        s2[r][tid + 1] = v ? h2[off] : 0.f;
    }
    if (tid < 10)                     { s1[tid][0] = 0.f;   s2[tid][0] = 0.f; }
    if (tid >= 128 && tid < 138)      { int r = tid - 128; s1[r][257] = 0.f; s2[r][257] = 0.f; }

    float wa[9], wb[9];
    #pragma unroll
    for (int i = 0; i < 9; i++) { wa[i] = wdw[g*9 + i]; wb[i] = wdw[(g+256)*9 + i]; }
    const float ba = bdw[g], bb2 = bdw[g + 256];
    __syncthreads();

    float acc1[8], acc2[8];
    #pragma unroll
    for (int i = 0; i < 8; i++) { acc1[i] = ba; acc2[i] = bb2; }

    const int c = tid;
    #pragma unroll
    for (int r = 0; r < 10; r++) {
        float x0 = s1[r][c], x1 = s1[r][c+1], x2 = s1[r][c+2];
        float z0 = s2[r][c], z1 = s2[r][c+1], z2 = s2[r][c+2];
        #pragma unroll
        for (int ky = 0; ky < 3; ky++) {
            int y = r - ky;                    // output row using s-row r with kernel row ky
            if (y >= 0 && y < 8) {
                acc1[y] += x0*wa[ky*3+0] + x1*wa[ky*3+1] + x2*wa[ky*3+2];
                acc2[y] += z0*wb[ky*3+0] + z1*wb[ky*3+1] + z2*wb[ky*3+2];
            }
        }
    }

    float* gp = &g_g[(b * 256 + g) * HW + h0 * IMG + tid];
    #pragma unroll
    for (int y = 0; y < 8; y++) {
        float a  = acc1[y];
        float ge = 0.5f * a * (1.0f + erff(a * 0.70710678118654752f));
        gp[y * IMG] = ge * acc2[y];
    }
}

// ============================================================
// Kernel 3: project_out  y[b,o,p] = b_out[o] + sum_g w_out[o,g]*g[b,g,p]
// M=64, K=256 (4 chunks), N=65536/batch. px tile 256, 8o x 8px FFMA2.
// grid (256,1,4), block 256.
// ============================================================
__global__ __launch_bounds__(256) void k_proj_out(
    const float* __restrict__ bias)
{
    extern __shared__ float dyn[];
    float* Xs = dyn;               // [k][px] stride 264
    float* Wt = dyn + 64 * 264;    // [k][o]  stride 68
    const int px0 = blockIdx.x * 256;
    const int b   = blockIdx.z;
    const int tid = threadIdx.x;
    const int tx  = tid & 31, ty = tid >> 5;

    unsigned long long acc[8][4];
    #pragma unroll
    for (int i = 0; i < 8; i++)
        #pragma unroll
        for (int j = 0; j < 4; j++) acc[i][j] = 0ull;

    for (int kc = 0; kc < 4; kc++) {
        const int k0 = kc * 64;
        #pragma unroll
        for (int i = 0; i < 4; i++) {
            int idx = tid + i * 256;
            int kk  = idx >> 4;
            int j4  = idx & 15;
            *(float4*)&Wt[kk * 68 + j4 * 4] =
                *(const float4*)(g_w2t + (k0 + kk) * 64 + j4 * 4);
        }
        const float* gb = g_g + (b * 256 + k0) * HW + px0;
        #pragma unroll
        for (int i = 0; i < 16; i++) {
            int idx = tid + i * 256;
            int kk  = idx >> 6;
            int j4  = idx & 63;
            *(float4*)&Xs[kk * 264 + j4 * 4] = *(const float4*)(gb + kk * HW + j4 * 4);
        }
        __syncthreads();

        #pragma unroll 8
        for (int k = 0; k < 64; k++) {
            float4 a0 = *(float4*)&Wt[k * 68 + ty * 8];
            float4 a1 = *(float4*)&Wt[k * 68 + ty * 8 + 4];
            longlong2 b0 = *(longlong2*)&Xs[k * 264 + tx * 4];
            longlong2 b1 = *(longlong2*)&Xs[k * 264 + 128 + tx * 4];
            unsigned long long p0 = (unsigned long long)b0.x;
            unsigned long long p1 = (unsigned long long)b0.y;
            unsigned long long p2 = (unsigned long long)b1.x;
            unsigned long long p3 = (unsigned long long)b1.y;
            unsigned long long a2[8];
            DUP2(a2[0], a0.x); DUP2(a2[1], a0.y); DUP2(a2[2], a0.z); DUP2(a2[3], a0.w);
            DUP2(a2[4], a1.x); DUP2(a2[5], a1.y); DUP2(a2[6], a1.z); DUP2(a2[7], a1.w);
            #pragma unroll
            for (int i = 0; i < 8; i++) {
                FFMA2(acc[i][0], a2[i], p0);
                FFMA2(acc[i][1], a2[i], p1);
                FFMA2(acc[i][2], a2[i], p2);
                FFMA2(acc[i][3], a2[i], p3);
            }
        }
        __syncthreads();
    }
    #pragma unroll
    for (int i = 0; i < 8; i++) {
        int o = ty * 8 + i;
        float bz = bias[o];
        unsigned r0, r1, r2, r3, r4, r5, r6, r7;
        UNPK2(r0, r1, acc[i][0]); UNPK2(r2, r3, acc[i][1]);
        UNPK2(r4, r5, acc[i][2]); UNPK2(r6, r7, acc[i][3]);
        float4 v0 = make_float4(__uint_as_float(r0) + bz, __uint_as_float(r1) + bz,
                                __uint_as_float(r2) + bz, __uint_as_float(r3) + bz);
        float4 v1 = make_float4(__uint_as_float(r4) + bz, __uint_as_float(r5) + bz,
                                __uint_as_float(r6) + bz, __uint_as_float(r7) + bz);
        float* op = &g_y[(b * 64 + o) * HW + px0];
        *(float4*)(op + tx * 4)       = v0;
        *(float4*)(op + 128 + tx * 4) = v1;
    }
}

// ============================================================
// Kernel 4: build spatial circular kernel (unchanged)
// ============================================================
__global__ void k_build_filter(const float* __restrict__ f)
{
    int t = blockIdx.x * 256 + threadIdx.x;
    if (t >= 4096) return;
    int ch = t >> 6;
    int a  = (t >> 3) & 7;
    int bb = t & 7;
    const float R = 0.70710678118654752f;
    const float ctab[8] = {1.f, R, 0.f, -R, -1.f, -R, 0.f, R};
    float s = 0.f;
    #pragma unroll
    for (int k1 = 0; k1 < 8; k1++)
        #pragma unroll
        for (int k2 = 0; k2 < 8; k2++) {
            float G = (k2 <= 4) ? f[ch*40 + k1*5 + k2]
                                : f[ch*40 + ((8-k1) & 7)*5 + (8 - k2)];
            s += G * ctab[(k1*a + k2*bb) & 7];
        }
    g_K[t] = s * (1.f / 64.f);
}

// ============================================================
// Kernel 5: per-8x8-patch circular convolution (unchanged)
// ============================================================
__global__ __launch_bounds__(256) void k_patch(float* __restrict__ out)
{
    __shared__ float s[8][257];
    __shared__ float Ks[64];
    const int h0 = blockIdx.y * 8;
    const int b  = blockIdx.z >> 6;
    const int ch = blockIdx.z & 63;
    const int tid = threadIdx.x;

    const float* yc = g_y + (b * 64 + ch) * HW;
    if (tid < 64) Ks[tid] = g_K[ch * 64 + tid];
    #pragma unroll
    for (int i = 0; i < 8; i++) {
        int idx = tid + i * 256;
        int r = idx >> 8, c = idx & 255;
        s[r][c] = yc[(h0 + r) * IMG + c];
    }
    __syncthreads();

    const int n1 = tid & 7;
    const int pw = tid >> 3;
    const int pb = pw * 8;
    float acc[8] = {};
    #pragma unroll
    for (int d1 = 0; d1 < 8; d1++) {
        int r = (n1 - d1) & 7;
        float riv[8];
        #pragma unroll
        for (int j = 0; j < 8; j++) riv[j] = s[r][pb + j];
        #pragma unroll
        for (int d2 = 0; d2 < 8; d2++) {
            float kv = Ks[d1*8 + d2];
            #pragma unroll
            for (int c2 = 0; c2 < 8; c2++)
                acc[c2] += kv * riv[(c2 - d2) & 7];
        }
    }
    float* op = out + (b * 64 + ch) * HW + (h0 + n1) * IMG + pb;
    *(float4*)op       = make_float4(acc[0], acc[1], acc[2], acc[3]);
    *(float4*)(op + 4) = make_float4(acc[4], acc[5], acc[6], acc[7]);
}

// ============================================================
extern "C" void kernel_launch(void* const* d_in, const int* in_sizes, int n_in,
                              void* d_out, int out_size)
{
    const float* x     = (const float*)d_in[0];
    const float* w_in  = (const float*)d_in[1];
    const float* b_in  = (const float*)d_in[2];
    const float* w_dw  = (const float*)d_in[3];
    const float* b_dw  = (const float*)d_in[4];
    const float* w_out = (const float*)d_in[5];
    const float* b_out = (const float*)d_in[6];
    const float* fftf  = (const float*)d_in[7];
    float* out = (float*)d_out;

    cudaFuncSetAttribute(k_proj_in,  cudaFuncAttributeMaxDynamicSharedMemorySize, PI_SMEM);
    cudaFuncSetAttribute(k_proj_out, cudaFuncAttributeMaxDynamicSharedMemorySize, PO_SMEM);

    k_build_filter<<<16, 256>>>(fftf);
    k_transpose<<<128, 256>>>(w_in, w_out);
    k_proj_in<<<dim3(512, 1, 4), 256, PI_SMEM>>>(x, b_in);
    k_dw_glu<<<dim3(32, 1024), 256>>>(w_dw, b_dw);
    k_proj_out<<<dim3(256, 1, 4), 256, PO_SMEM>>>(b_out);
    k_patch<<<dim3(1, 32, 256), 256>>>(out);
}

// round 7
// speedup vs baseline: 1.3503x; 1.0639x over previous
#include <cuda_runtime.h>
#include <cuda_fp16.h>
#include <math.h>

#define HW 65536           // 256*256
#define IMG 256

// ---- scratch (device globals: allocation-free contract) ----
__device__ __half g_h16[134217728]; // [4][512][65536] project_in out (fp16, 256 MB)
__device__ __half g_g16[67108864];  // [4][256][65536] glu out        (fp16, 128 MB)
__device__ float  g_y[16777216];    // [4][64][65536]  project_out out (64 MB)
__device__ float  g_K[4096];        // [64][8][8]      spatial circular kernel
__device__ float  g_wt[32768];      // w_in^T  [c=64][o=512]
__device__ float  g_w2t[16384];     // w_out^T [k=256][o=64]

// packed fp32x2 FMA (Blackwell FFMA2; 2x fp32 rate vs scalar FFMA)
#define FFMA2(d, a, b) asm("fma.rn.f32x2 %0, %1, %2, %0;" : "+l"(d) : "l"(a), "l"(b))
#define DUP2(d, f)     asm("mov.b64 %0, {%1, %1};" : "=l"(d) : "r"(__float_as_uint(f)))
#define UNPK2(lo, hi, d) asm("mov.b64 {%0, %1}, %2;" : "=r"(lo), "=r"(hi) : "l"(d))

#define PI_SMEM  (2 * 64 * 132 * 4)          // proj_in: Xs[64][132] + Wt[64][132]
#define PO_SMEM  ((64 * 264 + 64 * 68) * 4)  // proj_out: Xs[64][264] + Wt[64][68]

// ============================================================
// Kernel 0: one-time weight transposes (tiny)
// ============================================================
__global__ void k_transpose(const float* __restrict__ w_in,
                            const float* __restrict__ w_out)
{
    int t = blockIdx.x * 256 + threadIdx.x;
    if (t < 32768) { int o = t >> 6, c = t & 63;  g_wt[c * 512 + o] = w_in[t]; }
    if (t < 16384) { int o = t >> 8, k = t & 255; g_w2t[k * 64 + o] = w_out[t]; }
}

// ============================================================
// Kernel 1: project_in  h[b,o,p] = b_in[o] + sum_c w_in[o,c]*x[b,c,p]
// M=512, K=64, N=65536/batch. px tile 128 (X loaded once), 4 o-chunks of 128.
// Thread tile 8o x 8px, FFMA2. Output stored fp16. grid (512,1,4), block 256.
// ============================================================
__global__ __launch_bounds__(256) void k_proj_in(
    const float* __restrict__ x, const float* __restrict__ bias)
{
    extern __shared__ float dyn[];
    float* Xs = dyn;               // [c][px] stride 132
    float* Wt = dyn + 64 * 132;    // [c][o]  stride 132
    const int px0 = blockIdx.x * 128;
    const int b   = blockIdx.z;
    const int tid = threadIdx.x;
    const int tx  = tid & 15, ty = tid >> 4;

    const float* xb = x + (b * 64) * HW + px0;
    #pragma unroll
    for (int i = 0; i < 8; i++) {
        int idx = tid + i * 256;
        int c   = idx >> 5;
        int j4  = idx & 31;
        *(float4*)&Xs[c * 132 + j4 * 4] = *(const float4*)(xb + c * HW + j4 * 4);
    }

    for (int oc = 0; oc < 4; oc++) {
        const int o0 = oc * 128;
        #pragma unroll
        for (int i = 0; i < 8; i++) {
            int idx = tid + i * 256;
            int c   = idx >> 5;
            int j4  = idx & 31;
            *(float4*)&Wt[c * 132 + j4 * 4] =
                *(const float4*)(g_wt + c * 512 + o0 + j4 * 4);
        }
        __syncthreads();

        unsigned long long acc[8][4];
        #pragma unroll
        for (int i = 0; i < 8; i++)
            #pragma unroll
            for (int j = 0; j < 4; j++) acc[i][j] = 0ull;

        #pragma unroll 8
        for (int k = 0; k < 64; k++) {
            float4 a0 = *(float4*)&Wt[k * 132 + ty * 8];
            float4 a1 = *(float4*)&Wt[k * 132 + ty * 8 + 4];
            longlong2 b0 = *(longlong2*)&Xs[k * 132 + tx * 4];
            longlong2 b1 = *(longlong2*)&Xs[k * 132 + 64 + tx * 4];
            unsigned long long p0 = (unsigned long long)b0.x;
            unsigned long long p1 = (unsigned long long)b0.y;
            unsigned long long p2 = (unsigned long long)b1.x;
            unsigned long long p3 = (unsigned long long)b1.y;
            unsigned long long a2[8];
            DUP2(a2[0], a0.x); DUP2(a2[1], a0.y); DUP2(a2[2], a0.z); DUP2(a2[3], a0.w);
            DUP2(a2[4], a1.x); DUP2(a2[5], a1.y); DUP2(a2[6], a1.z); DUP2(a2[7], a1.w);
            #pragma unroll
            for (int i = 0; i < 8; i++) {
                FFMA2(acc[i][0], a2[i], p0);
                FFMA2(acc[i][1], a2[i], p1);
                FFMA2(acc[i][2], a2[i], p2);
                FFMA2(acc[i][3], a2[i], p3);
            }
        }
        __syncthreads();

        #pragma unroll
        for (int i = 0; i < 8; i++) {
            int o = o0 + ty * 8 + i;
            float bz = bias[o];
            unsigned r0, r1, r2, r3, r4, r5, r6, r7;
            UNPK2(r0, r1, acc[i][0]); UNPK2(r2, r3, acc[i][1]);
            UNPK2(r4, r5, acc[i][2]); UNPK2(r6, r7, acc[i][3]);
            __half2 h0 = __floats2half2_rn(__uint_as_float(r0) + bz, __uint_as_float(r1) + bz);
            __half2 h1 = __floats2half2_rn(__uint_as_float(r2) + bz, __uint_as_float(r3) + bz);
            __half2 h2 = __floats2half2_rn(__uint_as_float(r4) + bz, __uint_as_float(r5) + bz);
            __half2 h3 = __floats2half2_rn(__uint_as_float(r6) + bz, __uint_as_float(r7) + bz);
            __half* hp = g_h16 + (size_t)(b * 512 + o) * HW + px0;
            *(__half2*)(hp + tx * 4)          = h0;
            *(__half2*)(hp + tx * 4 + 2)      = h1;
            *(__half2*)(hp + 64 + tx * 4)     = h2;
            *(__half2*)(hp + 64 + tx * 4 + 2) = h3;
        }
    }
}

// ============================================================
// Kernel 2: depthwise 3x3 (SAME) + bias + exact-GELU gate — full-row tiles.
// Reads fp16 g_h16, computes fp32, writes fp16 g_g16.
// grid (32, 1024=B*256), block 256.
// ============================================================
__global__ __launch_bounds__(256) void k_dw_glu(
    const float* __restrict__ wdw, const float* __restrict__ bdw)
{
    __shared__ float s1[10][264];
    __shared__ float s2[10][264];
    const int h0 = blockIdx.x * 8;
    const int b  = blockIdx.y >> 8;
    const int g  = blockIdx.y & 255;
    const int tid = threadIdx.x;

    const __half* h1 = g_h16 + (size_t)(b * 512 + g) * HW;
    const __half* h2 = g_h16 + (size_t)(b * 512 + g + 256) * HW;

    #pragma unroll
    for (int r = 0; r < 10; r++) {
        int gy = h0 + r - 1;
        bool v = (gy >= 0) & (gy < IMG);
        int off = gy * IMG + tid;
        s1[r][tid + 1] = v ? __half2float(h1[off]) : 0.f;
        s2[r][tid + 1] = v ? __half2float(h2[off]) : 0.f;
    }
    if (tid < 10)                { s1[tid][0] = 0.f;   s2[tid][0] = 0.f; }
    if (tid >= 128 && tid < 138) { int r = tid - 128; s1[r][257] = 0.f; s2[r][257] = 0.f; }

    float wa[9], wb[9];
    #pragma unroll
    for (int i = 0; i < 9; i++) { wa[i] = wdw[g*9 + i]; wb[i] = wdw[(g+256)*9 + i]; }
    const float ba = bdw[g], bb2 = bdw[g + 256];
    __syncthreads();

    float acc1[8], acc2[8];
    #pragma unroll
    for (int i = 0; i < 8; i++) { acc1[i] = ba; acc2[i] = bb2; }

    const int c = tid;
    #pragma unroll
    for (int r = 0; r < 10; r++) {
        float x0 = s1[r][c], x1 = s1[r][c+1], x2 = s1[r][c+2];
        float z0 = s2[r][c], z1 = s2[r][c+1], z2 = s2[r][c+2];
        #pragma unroll
        for (int ky = 0; ky < 3; ky++) {
            int y = r - ky;
            if (y >= 0 && y < 8) {
                acc1[y] += x0*wa[ky*3+0] + x1*wa[ky*3+1] + x2*wa[ky*3+2];
                acc2[y] += z0*wb[ky*3+0] + z1*wb[ky*3+1] + z2*wb[ky*3+2];
            }
        }
    }

    __half* gp = g_g16 + (size_t)(b * 256 + g) * HW + h0 * IMG + tid;
    #pragma unroll
    for (int y = 0; y < 8; y++) {
        float a  = acc1[y];
        float ge = 0.5f * a * (1.0f + erff(a * 0.70710678118654752f));
        gp[y * IMG] = __float2half_rn(ge * acc2[y]);
    }
}

// ============================================================
// Kernel 3: project_out  y[b,o,p] = b_out[o] + sum_g w_out[o,g]*g[b,g,p]
// M=64, K=256 (4 chunks), N=65536/batch. Reads fp16 g_g16 (converted to fp32
// in smem). px tile 256, 8o x 8px FFMA2. grid (256,1,4), block 256.
// ============================================================
__global__ __launch_bounds__(256) void k_proj_out(
    const float* __restrict__ bias)
{
    extern __shared__ float dyn[];
    float* Xs = dyn;               // [k][px] stride 264
    float* Wt = dyn + 64 * 264;    // [k][o]  stride 68
    const int px0 = blockIdx.x * 256;
    const int b   = blockIdx.z;
    const int tid = threadIdx.x;
    const int tx  = tid & 31, ty = tid >> 5;

    unsigned long long acc[8][4];
    #pragma unroll
    for (int i = 0; i < 8; i++)
        #pragma unroll
        for (int j = 0; j < 4; j++) acc[i][j] = 0ull;

    for (int kc = 0; kc < 4; kc++) {
        const int k0 = kc * 64;
        #pragma unroll
        for (int i = 0; i < 4; i++) {
            int idx = tid + i * 256;
            int kk  = idx >> 4;
            int j4  = idx & 15;
            *(float4*)&Wt[kk * 68 + j4 * 4] =
                *(const float4*)(g_w2t + (k0 + kk) * 64 + j4 * 4);
        }
        // X chunk (64 k x 256 px) as fp16 -> fp32 smem
        const __half* gb = g_g16 + (size_t)(b * 256 + k0) * HW + px0;
        #pragma unroll
        for (int i = 0; i < 8; i++) {
            int idx = tid + i * 256;        // 0..2047
            int kk  = idx >> 5;             // 0..63
            int j8  = idx & 31;             // 32 groups of 8 halves = 256 px
            uint4 raw = *(const uint4*)(gb + kk * HW + j8 * 8);
            __half2* hp = (__half2*)&raw;
            float2 f0 = __half22float2(hp[0]);
            float2 f1 = __half22float2(hp[1]);
            float2 f2 = __half22float2(hp[2]);
            float2 f3 = __half22float2(hp[3]);
            float* dst = &Xs[kk * 264 + j8 * 8];
            *(float4*)dst       = make_float4(f0.x, f0.y, f1.x, f1.y);
            *(float4*)(dst + 4) = make_float4(f2.x, f2.y, f3.x, f3.y);
        }
        __syncthreads();

        #pragma unroll 8
        for (int k = 0; k < 64; k++) {
            float4 a0 = *(float4*)&Wt[k * 68 + ty * 8];
            float4 a1 = *(float4*)&Wt[k * 68 + ty * 8 + 4];
            longlong2 b0 = *(longlong2*)&Xs[k * 264 + tx * 4];
            longlong2 b1 = *(longlong2*)&Xs[k * 264 + 128 + tx * 4];
            unsigned long long p0 = (unsigned long long)b0.x;
            unsigned long long p1 = (unsigned long long)b0.y;
            unsigned long long p2 = (unsigned long long)b1.x;
            unsigned long long p3 = (unsigned long long)b1.y;
            unsigned long long a2[8];
            DUP2(a2[0], a0.x); DUP2(a2[1], a0.y); DUP2(a2[2], a0.z); DUP2(a2[3], a0.w);
            DUP2(a2[4], a1.x); DUP2(a2[5], a1.y); DUP2(a2[6], a1.z); DUP2(a2[7], a1.w);
            #pragma unroll
            for (int i = 0; i < 8; i++) {
                FFMA2(acc[i][0], a2[i], p0);
                FFMA2(acc[i][1], a2[i], p1);
                FFMA2(acc[i][2], a2[i], p2);
                FFMA2(acc[i][3], a2[i], p3);
            }
        }
        __syncthreads();
    }
    #pragma unroll
    for (int i = 0; i < 8; i++) {
        int o = ty * 8 + i;
        float bz = bias[o];
        unsigned r0, r1, r2, r3, r4, r5, r6, r7;
        UNPK2(r0, r1, acc[i][0]); UNPK2(r2, r3, acc[i][1]);
        UNPK2(r4, r5, acc[i][2]); UNPK2(r6, r7, acc[i][3]);
        float4 v0 = make_float4(__uint_as_float(r0) + bz, __uint_as_float(r1) + bz,
                                __uint_as_float(r2) + bz, __uint_as_float(r3) + bz);
        float4 v1 = make_float4(__uint_as_float(r4) + bz, __uint_as_float(r5) + bz,
                                __uint_as_float(r6) + bz, __uint_as_float(r7) + bz);
        float* op = &g_y[(b * 64 + o) * HW + px0];
        *(float4*)(op + tx * 4)       = v0;
        *(float4*)(op + 128 + tx * 4) = v1;
    }
}

// ============================================================
// Kernel 4: build spatial circular kernel (unchanged)
// ============================================================
__global__ void k_build_filter(const float* __restrict__ f)
{
    int t = blockIdx.x * 256 + threadIdx.x;
    if (t >= 4096) return;
    int ch = t >> 6;
    int a  = (t >> 3) & 7;
    int bb = t & 7;
    const float R = 0.70710678118654752f;
    const float ctab[8] = {1.f, R, 0.f, -R, -1.f, -R, 0.f, R};
    float s = 0.f;
    #pragma unroll
    for (int k1 = 0; k1 < 8; k1++)
        #pragma unroll
        for (int k2 = 0; k2 < 8; k2++) {
            float G = (k2 <= 4) ? f[ch*40 + k1*5 + k2]
                                : f[ch*40 + ((8-k1) & 7)*5 + (8 - k2)];
            s += G * ctab[(k1*a + k2*bb) & 7];
        }
    g_K[t] = s * (1.f / 64.f);
}

// ============================================================
// Kernel 5: per-8x8-patch circular convolution (unchanged)
// ============================================================
__global__ __launch_bounds__(256) void k_patch(float* __restrict__ out)
{
    __shared__ float s[8][257];
    __shared__ float Ks[64];
    const int h0 = blockIdx.y * 8;
    const int b  = blockIdx.z >> 6;
    const int ch = blockIdx.z & 63;
    const int tid = threadIdx.x;

    const float* yc = g_y + (b * 64 + ch) * HW;
    if (tid < 64) Ks[tid] = g_K[ch * 64 + tid];
    #pragma unroll
    for (int i = 0; i < 8; i++) {
        int idx = tid + i * 256;
        int r = idx >> 8, c = idx & 255;
        s[r][c] = yc[(h0 + r) * IMG + c];
    }
    __syncthreads();

    const int n1 = tid & 7;
    const int pw = tid >> 3;
    const int pb = pw * 8;
    float acc[8] = {};
    #pragma unroll
    for (int d1 = 0; d1 < 8; d1++) {
        int r = (n1 - d1) & 7;
        float riv[8];
        #pragma unroll
        for (int j = 0; j < 8; j++) riv[j] = s[r][pb + j];
        #pragma unroll
        for (int d2 = 0; d2 < 8; d2++) {
            float kv = Ks[d1*8 + d2];
            #pragma unroll
            for (int c2 = 0; c2 < 8; c2++)
                acc[c2] += kv * riv[(c2 - d2) & 7];
        }
    }
    float* op = out + (b * 64 + ch) * HW + (h0 + n1) * IMG + pb;
    *(float4*)op       = make_float4(acc[0], acc[1], acc[2], acc[3]);
    *(float4*)(op + 4) = make_float4(acc[4], acc[5], acc[6], acc[7]);
}

// ============================================================
extern "C" void kernel_launch(void* const* d_in, const int* in_sizes, int n_in,
                              void* d_out, int out_size)
{
    const float* x     = (const float*)d_in[0];
    const float* w_in  = (const float*)d_in[1];
    const float* b_in  = (const float*)d_in[2];
    const float* w_dw  = (const float*)d_in[3];
    const float* b_dw  = (const float*)d_in[4];
    const float* w_out = (const float*)d_in[5];
    const float* b_out = (const float*)d_in[6];
    const float* fftf  = (const float*)d_in[7];
    float* out = (float*)d_out;

    cudaFuncSetAttribute(k_proj_in,  cudaFuncAttributeMaxDynamicSharedMemorySize, PI_SMEM);
    cudaFuncSetAttribute(k_proj_out, cudaFuncAttributeMaxDynamicSharedMemorySize, PO_SMEM);

    k_build_filter<<<16, 256>>>(fftf);
    k_transpose<<<128, 256>>>(w_in, w_out);
    k_proj_in<<<dim3(512, 1, 4), 256, PI_SMEM>>>(x, b_in);
    k_dw_glu<<<dim3(32, 1024), 256>>>(w_dw, b_dw);
    k_proj_out<<<dim3(256, 1, 4), 256, PO_SMEM>>>(b_out);
    k_patch<<<dim3(1, 32, 256), 256>>>(out);
}

// round 9
// speedup vs baseline: 1.4193x; 1.0511x over previous
#include <cuda_runtime.h>
#include <cuda_fp16.h>
#include <math.h>

#define HW 65536           // 256*256
#define IMG 256

// ---- scratch (device globals: allocation-free contract) ----
__device__ __half g_h16[134217728]; // [4][512][65536] project_in out (fp16, 256 MB)
__device__ __half g_g16[67108864];  // [4][256][65536] glu out        (fp16, 128 MB)
__device__ float  g_y[16777216];    // [4][64][65536]  project_out out (64 MB)
__device__ float  g_K[4096];        // [64][8][8]      spatial circular kernel
__device__ float  g_wt[32768];      // w_in^T  [c=64][o=512]
__device__ float  g_w2t[16384];     // w_out^T [k=256][o=64]

// packed fp32x2 FMA (Blackwell FFMA2; 2x fp32 rate vs scalar FFMA)
#define FFMA2(d, a, b) asm("fma.rn.f32x2 %0, %1, %2, %0;" : "+l"(d) : "l"(a), "l"(b))
#define DUP2(d, f)     asm("mov.b64 %0, {%1, %1};" : "=l"(d) : "r"(__float_as_uint(f)))
#define PACK2(d, lo, hi) asm("mov.b64 %0, {%1, %2};" : "=l"(d) : "r"(__float_as_uint(lo)), "r"(__float_as_uint(hi)))
#define UNPK2(lo, hi, d) asm("mov.b64 {%0, %1}, %2;" : "=r"(lo), "=r"(hi) : "l"(d))

#define PI_SMEM  (2 * 64 * 132 * 4)          // proj_in: Xs[64][132] + Wt[64][132]
#define PO_SMEM  ((64 * 264 + 64 * 68) * 4)  // proj_out: Xs[64][264] + Wt[64][68]

// ============================================================
// Kernel 0: one-time weight transposes (tiny)
// ============================================================
__global__ void k_transpose(const float* __restrict__ w_in,
                            const float* __restrict__ w_out)
{
    int t = blockIdx.x * 256 + threadIdx.x;
    if (t < 32768) { int o = t >> 6, c = t & 63;  g_wt[c * 512 + o] = w_in[t]; }
    if (t < 16384) { int o = t >> 8, k = t & 255; g_w2t[k * 64 + o] = w_out[t]; }
}

// ============================================================
// Kernel 1: project_in  h[b,o,p] = b_in[o] + sum_c w_in[o,c]*x[b,c,p]
// M=512, K=64, N=65536/batch. px tile 128 (X loaded once), 4 o-chunks of 128.
// Thread tile 8o x 8px, FFMA2. Output stored fp16. grid (512,1,4), block 256.
// ============================================================
__global__ __launch_bounds__(256) void k_proj_in(
    const float* __restrict__ x, const float* __restrict__ bias)
{
    extern __shared__ float dyn[];
    float* Xs = dyn;               // [c][px] stride 132
    float* Wt = dyn + 64 * 132;    // [c][o]  stride 132
    const int px0 = blockIdx.x * 128;
    const int b   = blockIdx.z;
    const int tid = threadIdx.x;
    const int tx  = tid & 15, ty = tid >> 4;

    const float* xb = x + (b * 64) * HW + px0;
    #pragma unroll
    for (int i = 0; i < 8; i++) {
        int idx = tid + i * 256;
        int c   = idx >> 5;
        int j4  = idx & 31;
        *(float4*)&Xs[c * 132 + j4 * 4] = *(const float4*)(xb + c * HW + j4 * 4);
    }

    for (int oc = 0; oc < 4; oc++) {
        const int o0 = oc * 128;
        #pragma unroll
        for (int i = 0; i < 8; i++) {
            int idx = tid + i * 256;
            int c   = idx >> 5;
            int j4  = idx & 31;
            *(float4*)&Wt[c * 132 + j4 * 4] =
                *(const float4*)(g_wt + c * 512 + o0 + j4 * 4);
        }
        __syncthreads();

        unsigned long long acc[8][4];
        #pragma unroll
        for (int i = 0; i < 8; i++)
            #pragma unroll
            for (int j = 0; j < 4; j++) acc[i][j] = 0ull;

        #pragma unroll 8
        for (int k = 0; k < 64; k++) {
            float4 a0 = *(float4*)&Wt[k * 132 + ty * 8];
            float4 a1 = *(float4*)&Wt[k * 132 + ty * 8 + 4];
            longlong2 b0 = *(longlong2*)&Xs[k * 132 + tx * 4];
            longlong2 b1 = *(longlong2*)&Xs[k * 132 + 64 + tx * 4];
            unsigned long long p0 = (unsigned long long)b0.x;
            unsigned long long p1 = (unsigned long long)b0.y;
            unsigned long long p2 = (unsigned long long)b1.x;
            unsigned long long p3 = (unsigned long long)b1.y;
            unsigned long long a2[8];
            DUP2(a2[0], a0.x); DUP2(a2[1], a0.y); DUP2(a2[2], a0.z); DUP2(a2[3], a0.w);
            DUP2(a2[4], a1.x); DUP2(a2[5], a1.y); DUP2(a2[6], a1.z); DUP2(a2[7], a1.w);
            #pragma unroll
            for (int i = 0; i < 8; i++) {
                FFMA2(acc[i][0], a2[i], p0);
                FFMA2(acc[i][1], a2[i], p1);
                FFMA2(acc[i][2], a2[i], p2);
                FFMA2(acc[i][3], a2[i], p3);
            }
        }
        __syncthreads();

        #pragma unroll
        for (int i = 0; i < 8; i++) {
            int o = o0 + ty * 8 + i;
            float bz = bias[o];
            unsigned r0, r1, r2, r3, r4, r5, r6, r7;
            UNPK2(r0, r1, acc[i][0]); UNPK2(r2, r3, acc[i][1]);
            UNPK2(r4, r5, acc[i][2]); UNPK2(r6, r7, acc[i][3]);
            __half2 h0 = __floats2half2_rn(__uint_as_float(r0) + bz, __uint_as_float(r1) + bz);
            __half2 h1 = __floats2half2_rn(__uint_as_float(r2) + bz, __uint_as_float(r3) + bz);
            __half2 h2 = __floats2half2_rn(__uint_as_float(r4) + bz, __uint_as_float(r5) + bz);
            __half2 h3 = __floats2half2_rn(__uint_as_float(r6) + bz, __uint_as_float(r7) + bz);
            __half* hp = g_h16 + (size_t)(b * 512 + o) * HW + px0;
            *(__half2*)(hp + tx * 4)          = h0;
            *(__half2*)(hp + tx * 4 + 2)      = h1;
            *(__half2*)(hp + 64 + tx * 4)     = h2;
            *(__half2*)(hp + 64 + tx * 4 + 2) = h3;
        }
    }
}

// ============================================================
// Kernel 2: depthwise 3x3 (SAME) + bias + exact-GELU gate — packed v3.
// Tile 16 rows x 256 cols. Threads: 128 column-pairs x 2 row-groups(8 rows).
// All gmem IO as __half2; conv accumulates column pairs in f32x2 via FFMA2.
// grid (16, 1024=B*256), block 256.
// ============================================================
__global__ __launch_bounds__(256) void k_dw_glu(
    const float* __restrict__ wdw, const float* __restrict__ bdw)
{
    __shared__ float s1[18][260];   // cols: [0..1]=left pad (col 1 = x[-1]), [2..257]=x[0..255], [258]=x[256]
    __shared__ float s2[18][260];
    const int h0 = blockIdx.x * 16;
    const int b  = blockIdx.y >> 8;
    const int g  = blockIdx.y & 255;
    const int tid = threadIdx.x;
    const int tc  = tid & 127;      // column-pair index: owns cols 2tc, 2tc+1
    const int rg  = tid >> 7;       // row group: owns output rows rg*8 .. rg*8+7

    // cooperative load: warps 0-3 (rg=0) fill s1, warps 4-7 fill s2
    {
        const __half* src = rg ? (g_h16 + (size_t)(b * 512 + g + 256) * HW)
                               : (g_h16 + (size_t)(b * 512 + g) * HW);
        float (*sf)[260] = rg ? s2 : s1;
        #pragma unroll
        for (int r = 0; r < 18; r++) {
            int gy = h0 + r - 1;
            float2 f = make_float2(0.f, 0.f);
            if (gy >= 0 && gy < IMG)
                f = __half22float2(*(const __half2*)(src + gy * IMG + tc * 2));
            *(float2*)&sf[r][2 + tc * 2] = f;
        }
        if (tc < 18) { sf[tc][1] = 0.f; sf[tc][258] = 0.f; }
    }

    // packed weights (lane-duplicated)
    unsigned long long w1p[9], w2p[9];
    #pragma unroll
    for (int i = 0; i < 9; i++) {
        DUP2(w1p[i], wdw[g * 9 + i]);
        DUP2(w2p[i], wdw[(g + 256) * 9 + i]);
    }
    unsigned long long binit1, binit2;
    DUP2(binit1, bdw[g]); DUP2(binit2, bdw[g + 256]);
    __syncthreads();

    unsigned long long acc1[8], acc2[8];
    #pragma unroll
    for (int i = 0; i < 8; i++) { acc1[i] = binit1; acc2[i] = binit2; }

    const int cb = tc * 2;          // smem idx of col c0-2
    const int r0 = rg * 8;
    #pragma unroll
    for (int r = 0; r < 10; r++) {
        const int sr = r0 + r;
        float2 q0 = *(float2*)&s1[sr][cb];       // cols c0-2, c0-1
        float2 q1 = *(float2*)&s1[sr][cb + 2];   // cols c0,   c0+1
        float2 q2 = *(float2*)&s1[sr][cb + 4];   // cols c0+2, c0+3
        float2 u0 = *(float2*)&s2[sr][cb];
        float2 u1 = *(float2*)&s2[sr][cb + 2];
        float2 u2 = *(float2*)&s2[sr][cb + 4];
        unsigned long long pA1, pB1, pC1, pA2, pB2, pC2;
        PACK2(pA1, q0.y, q1.x); PACK2(pB1, q1.x, q1.y); PACK2(pC1, q1.y, q2.x);
        PACK2(pA2, u0.y, u1.x); PACK2(pB2, u1.x, u1.y); PACK2(pC2, u1.y, u2.x);
        #pragma unroll
        for (int ky = 0; ky < 3; ky++) {
            int y = r - ky;
            if (y >= 0 && y < 8) {
                FFMA2(acc1[y], w1p[ky*3+0], pA1);
                FFMA2(acc1[y], w1p[ky*3+1], pB1);
                FFMA2(acc1[y], w1p[ky*3+2], pC1);
                FFMA2(acc2[y], w2p[ky*3+0], pA2);
                FFMA2(acc2[y], w2p[ky*3+1], pB2);
                FFMA2(acc2[y], w2p[ky*3+2], pC2);
            }
        }
    }

    __half* gp = g_g16 + (size_t)(b * 256 + g) * HW + (h0 + r0) * IMG + tc * 2;
    #pragma unroll
    for (int y = 0; y < 8; y++) {
        unsigned a_lo, a_hi, m_lo, m_hi;
        UNPK2(a_lo, a_hi, acc1[y]);
        UNPK2(m_lo, m_hi, acc2[y]);
        float au = __uint_as_float(a_lo), av = __uint_as_float(a_hi);
        float geu = 0.5f * au * (1.0f + erff(au * 0.70710678118654752f));
        float gev = 0.5f * av * (1.0f + erff(av * 0.70710678118654752f));
        *(__half2*)(gp + y * IMG) =
            __floats2half2_rn(geu * __uint_as_float(m_lo), gev * __uint_as_float(m_hi));
    }
}

// ============================================================
// Kernel 3: project_out  y[b,o,p] = b_out[o] + sum_g w_out[o,g]*g[b,g,p]
// M=64, K=256 (4 chunks), N=65536/batch. Reads fp16 g_g16 (converted to fp32
// in smem). px tile 256, 8o x 8px FFMA2. grid (256,1,4), block 256.
// ============================================================
__global__ __launch_bounds__(256) void k_proj_out(
    const float* __restrict__ bias)
{
    extern __shared__ float dyn[];
    float* Xs = dyn;               // [k][px] stride 264
    float* Wt = dyn + 64 * 264;    // [k][o]  stride 68
    const int px0 = blockIdx.x * 256;
    const int b   = blockIdx.z;
    const int tid = threadIdx.x;
    const int tx  = tid & 31, ty = tid >> 5;

    unsigned long long acc[8][4];
    #pragma unroll
    for (int i = 0; i < 8; i++)
        #pragma unroll
        for (int j = 0; j < 4; j++) acc[i][j] = 0ull;

    for (int kc = 0; kc < 4; kc++) {
        const int k0 = kc * 64;
        #pragma unroll
        for (int i = 0; i < 4; i++) {
            int idx = tid + i * 256;
            int kk  = idx >> 4;
            int j4  = idx & 15;
            *(float4*)&Wt[kk * 68 + j4 * 4] =
                *(const float4*)(g_w2t + (k0 + kk) * 64 + j4 * 4);
        }
        // X chunk (64 k x 256 px) as fp16 -> fp32 smem
        const __half* gb = g_g16 + (size_t)(b * 256 + k0) * HW + px0;
        #pragma unroll
        for (int i = 0; i < 8; i++) {
            int idx = tid + i * 256;        // 0..2047
            int kk  = idx >> 5;             // 0..63
            int j8  = idx & 31;             // 32 groups of 8 halves = 256 px
            uint4 raw = *(const uint4*)(gb + kk * HW + j8 * 8);
            __half2* hp = (__half2*)&raw;
            float2 f0 = __half22float2(hp[0]);
            float2 f1 = __half22float2(hp[1]);
            float2 f2 = __half22float2(hp[2]);
            float2 f3 = __half22float2(hp[3]);
            float* dst = &Xs[kk * 264 + j8 * 8];
            *(float4*)dst       = make_float4(f0.x, f0.y, f1.x, f1.y);
            *(float4*)(dst + 4) = make_float4(f2.x, f2.y, f3.x, f3.y);
        }
        __syncthreads();

        #pragma unroll 8
        for (int k = 0; k < 64; k++) {
            float4 a0 = *(float4*)&Wt[k * 68 + ty * 8];
            float4 a1 = *(float4*)&Wt[k * 68 + ty * 8 + 4];
            longlong2 b0 = *(longlong2*)&Xs[k * 264 + tx * 4];
            longlong2 b1 = *(longlong2*)&Xs[k * 264 + 128 + tx * 4];
            unsigned long long p0 = (unsigned long long)b0.x;
            unsigned long long p1 = (unsigned long long)b0.y;
            unsigned long long p2 = (unsigned long long)b1.x;
            unsigned long long p3 = (unsigned long long)b1.y;
            unsigned long long a2[8];
            DUP2(a2[0], a0.x); DUP2(a2[1], a0.y); DUP2(a2[2], a0.z); DUP2(a2[3], a0.w);
            DUP2(a2[4], a1.x); DUP2(a2[5], a1.y); DUP2(a2[6], a1.z); DUP2(a2[7], a1.w);
            #pragma unroll
            for (int i = 0; i < 8; i++) {
                FFMA2(acc[i][0], a2[i], p0);
                FFMA2(acc[i][1], a2[i], p1);
                FFMA2(acc[i][2], a2[i], p2);
                FFMA2(acc[i][3], a2[i], p3);
            }
        }
        __syncthreads();
    }
    #pragma unroll
    for (int i = 0; i < 8; i++) {
        int o = ty * 8 + i;
        float bz = bias[o];
        unsigned r0, r1, r2, r3, r4, r5, r6, r7;
        UNPK2(r0, r1, acc[i][0]); UNPK2(r2, r3, acc[i][1]);
        UNPK2(r4, r5, acc[i][2]); UNPK2(r6, r7, acc[i][3]);
        float4 v0 = make_float4(__uint_as_float(r0) + bz, __uint_as_float(r1) + bz,
                                __uint_as_float(r2) + bz, __uint_as_float(r3) + bz);
        float4 v1 = make_float4(__uint_as_float(r4) + bz, __uint_as_float(r5) + bz,
                                __uint_as_float(r6) + bz, __uint_as_float(r7) + bz);
        float* op = &g_y[(b * 64 + o) * HW + px0];
        *(float4*)(op + tx * 4)       = v0;
        *(float4*)(op + 128 + tx * 4) = v1;
    }
}

// ============================================================
// Kernel 4: build spatial circular kernel (unchanged)
// ============================================================
__global__ void k_build_filter(const float* __restrict__ f)
{
    int t = blockIdx.x * 256 + threadIdx.x;
    if (t >= 4096) return;
    int ch = t >> 6;
    int a  = (t >> 3) & 7;
    int bb = t & 7;
    const float R = 0.70710678118654752f;
    const float ctab[8] = {1.f, R, 0.f, -R, -1.f, -R, 0.f, R};
    float s = 0.f;
    #pragma unroll
    for (int k1 = 0; k1 < 8; k1++)
        #pragma unroll
        for (int k2 = 0; k2 < 8; k2++) {
            float G = (k2 <= 4) ? f[ch*40 + k1*5 + k2]
                                : f[ch*40 + ((8-k1) & 7)*5 + (8 - k2)];
            s += G * ctab[(k1*a + k2*bb) & 7];
        }
    g_K[t] = s * (1.f / 64.f);
}

// ============================================================
// Kernel 5: per-8x8-patch circular convolution (unchanged)
// ============================================================
__global__ __launch_bounds__(256) void k_patch(float* __restrict__ out)
{
    __shared__ float s[8][257];
    __shared__ float Ks[64];
    const int h0 = blockIdx.y * 8;
    const int b  = blockIdx.z >> 6;
    const int ch = blockIdx.z & 63;
    const int tid = threadIdx.x;

    const float* yc = g_y + (b * 64 + ch) * HW;
    if (tid < 64) Ks[tid] = g_K[ch * 64 + tid];
    #pragma unroll
    for (int i = 0; i < 8; i++) {
        int idx = tid + i * 256;
        int r = idx >> 8, c = idx & 255;
        s[r][c] = yc[(h0 + r) * IMG + c];
    }
    __syncthreads();

    const int n1 = tid & 7;
    const int pw = tid >> 3;
    const int pb = pw * 8;
    float acc[8] = {};
    #pragma unroll
    for (int d1 = 0; d1 < 8; d1++) {
        int r = (n1 - d1) & 7;
        float riv[8];
        #pragma unroll
        for (int j = 0; j < 8; j++) riv[j] = s[r][pb + j];
        #pragma unroll
        for (int d2 = 0; d2 < 8; d2++) {
            float kv = Ks[d1*8 + d2];
            #pragma unroll
            for (int c2 = 0; c2 < 8; c2++)
                acc[c2] += kv * riv[(c2 - d2) & 7];
        }
    }
    float* op = out + (b * 64 + ch) * HW + (h0 + n1) * IMG + pb;
    *(float4*)op       = make_float4(acc[0], acc[1], acc[2], acc[3]);
    *(float4*)(op + 4) = make_float4(acc[4], acc[5], acc[6], acc[7]);
}

// ============================================================
extern "C" void kernel_launch(void* const* d_in, const int* in_sizes, int n_in,
                              void* d_out, int out_size)
{
    const float* x     = (const float*)d_in[0];
    const float* w_in  = (const float*)d_in[1];
    const float* b_in  = (const float*)d_in[2];
    const float* w_dw  = (const float*)d_in[3];
    const float* b_dw  = (const float*)d_in[4];
    const float* w_out = (const float*)d_in[5];
    const float* b_out = (const float*)d_in[6];
    const float* fftf  = (const float*)d_in[7];
    float* out = (float*)d_out;

    cudaFuncSetAttribute(k_proj_in,  cudaFuncAttributeMaxDynamicSharedMemorySize, PI_SMEM);
    cudaFuncSetAttribute(k_proj_out, cudaFuncAttributeMaxDynamicSharedMemorySize, PO_SMEM);

    k_build_filter<<<16, 256>>>(fftf);
    k_transpose<<<128, 256>>>(w_in, w_out);
    k_proj_in<<<dim3(512, 1, 4), 256, PI_SMEM>>>(x, b_in);
    k_dw_glu<<<dim3(16, 1024), 256>>>(w_dw, b_dw);
    k_proj_out<<<dim3(256, 1, 4), 256, PO_SMEM>>>(b_out);
    k_patch<<<dim3(1, 32, 256), 256>>>(out);
}